// round 13
// baseline (speedup 1.0000x reference)
#include <cuda_runtime.h>
#include <stdint.h>

// ---------------------------------------------------------------------------
// ToDenseBEVConvolution: out[b][c][x][y] += sum_i features[n][i] * K[z_n][i][c]
// C_IN = C_OUT = 64, 32 kernel matrices, BEV 256x256, batch 4, N = 100000.
//
// Pipeline (4 launches, all graph-capturable, no allocations):
//   k_hist     : per-block SMEM histogram over z buckets
//   k_scan     : single block: per-block offsets + bucket starts + tile descs
//   k_scatter  : counting-sort scatter with SMEM cursors + grid-stride
//                zero-fill of the output (rides on idle store bandwidth)
//   k_main     : 128-point tiles, 128 thr, 8x8 register GEMM + RED scatter
// ---------------------------------------------------------------------------

#define C_IN    64
#define C_OUT   64
#define BEV_Y   256
#define BEV_XY  (256 * 256)
#define TILE_P  128
#define NZ      32
#define N_MAX   (1 << 20)
#define B_MAX   224
#define TILES_MAX (N_MAX / TILE_P + NZ + 2)
#define FSN     132   // padded row stride (floats) for transposed feature tile

// dynamic smem for k_main: Ks 4096 + Fs 64*FSN floats + base_s 128 ints
#define SMEM_MAIN_BYTES ((4096 + 64 * FSN) * 4 + TILE_P * 4)

// ---- scratch (static device globals; no runtime allocation) ----
__device__ int g_blkcnt[B_MAX * NZ];
__device__ int g_blkoff[B_MAX * NZ];
__device__ int g_ntiles;
__device__ int g_bucket[N_MAX];   // original point index, bucket-ordered
__device__ int g_base[N_MAX];     // flat output base (b*C_OUT*65536 + x*256 + y)
__device__ int g_tile_z[TILES_MAX];
__device__ int g_tile_start[TILES_MAX];
__device__ int g_tile_cnt[TILES_MAX];

// ---------------------------------------------------------------------------
__device__ __forceinline__ int detect_is64_warp(const void* coords) {
    const long long* c = (const long long*)coords;
    bool hz = ((c[threadIdx.x & 31] >> 32) == 0);
    unsigned m = __ballot_sync(0xffffffffu, hz);
    return (m == 0xffffffffu) ? 1 : 0;
}

// ---------------------------------------------------------------------------
__global__ void k_hist(const void* coords, const int* stride_p, int n, int chunk) {
    __shared__ int h[NZ];
    __shared__ int s_is64;
    int tid = threadIdx.x;
    if (tid < NZ) h[tid] = 0;
    if (tid < 32) {
        int v = detect_is64_warp(coords);
        if (tid == 0) s_is64 = v;
    }
    __syncthreads();

    int stride = max(*stride_p, 1);
    int lo = blockIdx.x * chunk;
    int hi = min(lo + chunk, n);
    if (s_is64) {
        const long long* c = (const long long*)coords;
        for (int i = lo + tid; i < hi; i += 256)
            atomicAdd(&h[(int)c[4ll * i + 1] / stride], 1);
    } else {
        const int* c = (const int*)coords;
        for (int i = lo + tid; i < hi; i += 256)
            atomicAdd(&h[c[4 * i + 1] / stride], 1);
    }
    __syncthreads();
    if (tid < NZ) g_blkcnt[blockIdx.x * NZ + tid] = h[tid];
}

// ---------------------------------------------------------------------------
__global__ void k_scan(int B) {
    __shared__ int s[B_MAX * NZ];          // 28 KB
    __shared__ int bstart[NZ];
    __shared__ int bcnt[NZ];
    __shared__ int tstart[NZ + 1];
    int tid = threadIdx.x;

    for (int t = tid; t < B * NZ; t += 1024) s[t] = g_blkcnt[t];
    __syncthreads();

    if (tid < NZ) {                         // per-z exclusive scan over blocks
        int z = tid, run = 0;
        for (int b = 0; b < B; b++) {
            int v = s[b * NZ + z];
            s[b * NZ + z] = run;
            run += v;
        }
        bcnt[z] = run;
    }
    __syncthreads();

    if (tid < 32) {                         // warp scan: bucket + tile offsets
        int z = tid;
        int c  = bcnt[z];
        int tl = (c + TILE_P - 1) / TILE_P;
        int co = c, to = tl;
        #pragma unroll
        for (int d = 1; d < 32; d <<= 1) {
            int v = __shfl_up_sync(0xffffffffu, co, d);
            int w = __shfl_up_sync(0xffffffffu, to, d);
            if (z >= d) { co += v; to += w; }
        }
        bstart[z] = co - c;
        tstart[z] = to - tl;
        if (z == 31) { tstart[NZ] = to; g_ntiles = to; }
    }
    __syncthreads();

    for (int t = tid; t < B * NZ; t += 1024) {
        int z = t & (NZ - 1);
        g_blkoff[t] = s[t] + bstart[z];
    }

    int ntiles = tstart[NZ];
    for (int t = tid; t < ntiles; t += 1024) {
        int lo = 0, hi = NZ - 1;            // largest z with tstart[z] <= t
        while (lo < hi) {
            int mid = (lo + hi + 1) >> 1;
            if (tstart[mid] <= t) lo = mid; else hi = mid - 1;
        }
        int local = t - tstart[lo];
        g_tile_z[t]     = lo;
        g_tile_start[t] = bstart[lo] + local * TILE_P;
        g_tile_cnt[t]   = min(TILE_P, bcnt[lo] - local * TILE_P);
    }
}

// ---------------------------------------------------------------------------
// Counting-sort scatter (SMEM cursors) + grid-stride zero-fill of the output.
// ---------------------------------------------------------------------------
__global__ void k_scatter(const void* coords, const int* stride_p, int n, int chunk,
                          float4* out4, int n4, int B) {
    __shared__ int cur[NZ];
    __shared__ int s_is64;
    int tid = threadIdx.x;
    if (tid < NZ) cur[tid] = g_blkoff[blockIdx.x * NZ + tid];
    if (tid < 32) {
        int v = detect_is64_warp(coords);
        if (tid == 0) s_is64 = v;
    }
    __syncthreads();

    int stride = max(*stride_p, 1);
    int lo = blockIdx.x * chunk;
    int hi = min(lo + chunk, n);
    for (int i = lo + tid; i < hi; i += 256) {
        int x, z, y, b;
        if (s_is64) {
            const long long* p = (const long long*)coords + 4ll * i;
            x = (int)p[0]; z = (int)p[1]; y = (int)p[2]; b = (int)p[3];
        } else {
            const int* p = (const int*)coords + 4 * i;
            x = p[0]; z = p[1]; y = p[2]; b = p[3];
        }
        int zq  = z / stride;
        int pos = atomicAdd(&cur[zq], 1);
        g_bucket[pos] = i;
        g_base[pos]   = b * (C_OUT * BEV_XY) + (x / stride) * BEV_Y + (y / stride);
    }

    // grid-stride zero-fill of the output (stream order guards k_main)
    const float4 z4 = make_float4(0.f, 0.f, 0.f, 0.f);
    for (int i = blockIdx.x * 256 + tid; i < n4; i += B * 256)
        out4[i] = z4;
}

// ---------------------------------------------------------------------------
// Main: one block = one tile of up to 128 points sharing kernel matrix z.
// 128 threads, each computes an 8x8 (points x channels) register block, then
// scatter-adds via REDs. 1.0 B LDS per FFMA (measured crossbar optimum);
// halved tile count halves per-tile K-staging traffic vs 64-pt tiles.
// ---------------------------------------------------------------------------
__global__ __launch_bounds__(128, 4)
void k_main(const float* __restrict__ features,
            const float* __restrict__ kern,
            float* __restrict__ out) {
    int tile = blockIdx.x;
    if (tile >= g_ntiles) return;

    extern __shared__ float smem[];
    float* Ks     = smem;                       // [64][64]       16 KB
    float* Fs     = smem + 4096;                // [64][FSN]      33 KB (transposed)
    int*   base_s = (int*)(smem + 4096 + 64 * FSN);  // [128]

    int tid   = threadIdx.x;
    int z     = g_tile_z[tile];
    int start = g_tile_start[tile];
    int cnt   = g_tile_cnt[tile];

    // Thread tid owns point tid of the tile.
    bool valid = tid < cnt;
    int pidx = valid ? g_bucket[start + tid] : 0;
    base_s[tid] = valid ? g_base[start + tid] : -1;

    // Stage K[z] (4096 floats) via float4, 128 threads x 8 iters
    {
        const float4* k4 = (const float4*)(kern + (size_t)z * C_IN * C_OUT);
        float4* ks4 = (float4*)Ks;
        #pragma unroll
        for (int t = 0; t < 8; t++) ks4[tid + t * 128] = k4[tid + t * 128];
    }
    // Stage transposed features: thread streams its own point's row; STS
    // addresses are (const + tid) across each warp -> conflict-free.
    {
        const float4* frow = (const float4*)(features + (size_t)pidx * C_IN);
        #pragma unroll
        for (int g = 0; g < 16; g++) {
            float4 f = valid ? frow[g] : make_float4(0.f, 0.f, 0.f, 0.f);
            int r = g * 4;
            Fs[(r + 0) * FSN + tid] = f.x;
            Fs[(r + 1) * FSN + tid] = f.y;
            Fs[(r + 2) * FSN + tid] = f.z;
            Fs[(r + 3) * FSN + tid] = f.w;
        }
    }
    __syncthreads();

    int tc = tid & 7;     // channel group (8 groups of 8 channels)
    int tp = tid >> 3;    // point group   (16 groups of 8 points)

    float acc[8][8];
    #pragma unroll
    for (int a = 0; a < 8; a++)
        #pragma unroll
        for (int c = 0; c < 8; c++) acc[a][c] = 0.f;

    const float4* fsA = (const float4*)&Fs[tp * 8];
    const float4* ksB = (const float4*)&Ks[tc * 8];

    #pragma unroll 8
    for (int i = 0; i < C_IN; i++) {
        float4 a0 = fsA[i * (FSN / 4)];
        float4 a1 = fsA[i * (FSN / 4) + 1];
        float4 b0 = ksB[i * (C_OUT / 4)];
        float4 b1 = ksB[i * (C_OUT / 4) + 1];
        float av[8] = {a0.x, a0.y, a0.z, a0.w, a1.x, a1.y, a1.z, a1.w};
        float bv[8] = {b0.x, b0.y, b0.z, b0.w, b1.x, b1.y, b1.z, b1.w};
        #pragma unroll
        for (int p = 0; p < 8; p++)
            #pragma unroll
            for (int c = 0; c < 8; c++)
                acc[p][c] += av[p] * bv[c];
    }

    // Scatter-add 8x8 results (REDs)
    #pragma unroll
    for (int pp = 0; pp < 8; pp++) {
        int base = base_s[tp * 8 + pp];
        if (base < 0) continue;
        #pragma unroll
        for (int cc = 0; cc < 8; cc++) {
            int c = tc * 8 + cc;
            atomicAdd(out + base + c * BEV_XY, acc[pp][cc]);
        }
    }
}

// ---------------------------------------------------------------------------
extern "C" void kernel_launch(void* const* d_in, const int* in_sizes, int n_in,
                              void* d_out, int out_size) {
    const float* features = (const float*)d_in[0];
    const float* kern     = (const float*)d_in[1];
    const void*  coords   = (const void*)d_in[2];
    const int*   stride_p = (const int*)d_in[3];
    float* out = (float*)d_out;

    int n = in_sizes[0] / C_IN;
    if (n > N_MAX) n = N_MAX;
    if (n < 1) return;

    // chunking for hist/scatter: ~512 pts/block
    int B = (n + 511) / 512;
    if (B > B_MAX) B = B_MAX;
    if (B < 1) B = 1;
    int chunk = (((n + B - 1) / B) + 255) & ~255;
    B = (n + chunk - 1) / chunk;

    static int attr_set = 0;
    if (!attr_set) {
        cudaFuncSetAttribute(k_main, cudaFuncAttributeMaxDynamicSharedMemorySize,
                             SMEM_MAIN_BYTES);
        attr_set = 1;
    }

    int n4 = out_size / 4;

    k_hist<<<B, 256>>>(coords, stride_p, n, chunk);
    k_scan<<<1, 1024>>>(B);
    k_scatter<<<B, 256>>>(coords, stride_p, n, chunk, (float4*)out, n4, B);

    int max_tiles = n / TILE_P + NZ + 1;
    k_main<<<max_tiles, 128, SMEM_MAIN_BYTES>>>(features, kern, out);
}